// round 14
// baseline (speedup 1.0000x reference)
#include <cuda_runtime.h>
#include <cstdint>

constexpr int N_  = 20000;
constexpr int E_  = 32768;
constexpr int R_  = 8;
constexpr long long NE_ = (long long)R_ * E_;   // 262144

// ---------------- scratch (static device globals; no runtime alloc) --------
__device__ __align__(16) float g_v[(size_t)NE_ * 128];   // silu(t1), later w
__device__ __align__(16) float g_ef[(size_t)NE_ * 128];  // edge features
__device__ __align__(16) float g_cd[(size_t)NE_ * 12];
__device__ __align__(16) float g_rad[(size_t)NE_ * 16];
__device__ __align__(16) float g_s[N_ * 12];
__device__ __align__(16) float g_agg[N_ * 128];
__device__ __align__(16) float g_cnt[N_];
__device__ __align__(16) float g_norm2[128];
__device__ __align__(16) float g_ninv[128];
__device__ __align__(16) float g_hnew[N_ * 128];
__device__ __align__(16) float g_z[N_ * 128];
__device__ int g_e64;   // 1 if edges are int64 on device

__device__ __forceinline__ float silu_f(float x) {
    return x / (1.0f + expf(-x));
}

// edge index accessor handling int32 or int64 storage
__device__ __forceinline__ int eidx(const int* e32, long long i) {
    if (g_e64) return (int)(((const long long*)e32)[i]);
    return e32[i];
}

// ---------------- dtype probe ----------------------------------------------
// If edges is int64 with values < 2^31, every odd 32-bit word is 0.
__global__ void k_detect(const int* __restrict__ e32) {
    if (threadIdx.x == 0 && blockIdx.x == 0) {
        int all0 = 1;
        for (int i = 1; i < 1024; i += 2)
            if (e32[i] != 0) { all0 = 0; break; }
        g_e64 = all0;
    }
}

// ---------------- zero accumulators ----------------------------------------
__global__ void k_zero() {
    int idx = blockIdx.x * blockDim.x + threadIdx.x;
    int stride = gridDim.x * blockDim.x;
    for (int i = idx; i < N_ * 128; i += stride) g_agg[i] = 0.f;
    for (int i = idx; i < N_ * 12; i += stride) g_s[i] = 0.f;
    for (int i = idx; i < N_; i += stride) g_cnt[i] = 0.f;
    if (idx < 128) g_norm2[idx] = 0.f;
}

// ---------------- geometry: cd, radial (raw), norm2, cnt -------------------
__global__ void k_geo(const float* __restrict__ coord,
                      const int* __restrict__ edges) {
    __shared__ float s_n[16];
    int tid = threadIdx.x;
    int r = blockIdx.y;
    long long e = (long long)blockIdx.x * 256 + tid;
    if (tid < 16) s_n[tid] = 0.f;
    __syncthreads();
    long long eg = (long long)r * E_ + e;
    int row = eidx(edges, (long long)(r * 2 + 0) * E_ + e);
    int col = eidx(edges, (long long)(r * 2 + 1) * E_ + e);
    float cd[4][3];
#pragma unroll
    for (int c = 0; c < 4; ++c)
#pragma unroll
        for (int a = 0; a < 3; ++a) {
            cd[c][a] = coord[(size_t)row * 12 + c * 3 + a]
                     - coord[(size_t)col * 12 + c * 3 + a];
            g_cd[(size_t)eg * 12 + c * 3 + a] = cd[c][a];
        }
#pragma unroll
    for (int c = 0; c < 4; ++c)
#pragma unroll
        for (int d = 0; d < 4; ++d) {
            float v = cd[c][0] * cd[d][0] + cd[c][1] * cd[d][1] + cd[c][2] * cd[d][2];
            g_rad[(size_t)eg * 16 + c * 4 + d] = v;
            atomicAdd(&s_n[c * 4 + d], v * v);
        }
    atomicAdd(&g_cnt[row], 1.f);
    __syncthreads();
    if (tid < 16) atomicAdd(&g_norm2[r * 16 + tid], s_n[tid]);
}

__global__ void k_norm() {
    int i = threadIdx.x;
    if (i < 128) g_ninv[i] = 1.0f / fmaxf(sqrtf(g_norm2[i]), 1e-12f);
}

// ---------------- message MLP layer 1: one block per edge ------------------
// g_v[eg,j] = silu( bm1[j] + sum_k h[row,k]Wm1[k,j] + sum_k h[col,k]Wm1[128+k,j]
//                 + sum_q radn[q]Wm1[256+q,j] + ea*Wm1[272,j] )
__global__ __launch_bounds__(128) void k_msg1(
    const int* __restrict__ edges, const float* __restrict__ h,
    const float* __restrict__ ea_, const float* __restrict__ Wm1,
    const float* __restrict__ bm1) {
    __shared__ float sh[128], sc[128], srad[16];
    __shared__ float sea;
    long long eg = blockIdx.x;
    int r = (int)(eg >> 15);
    long long e = eg & (E_ - 1);
    int j = threadIdx.x;
    int row = eidx(edges, (long long)(r * 2 + 0) * E_ + e);
    int col = eidx(edges, (long long)(r * 2 + 1) * E_ + e);
    sh[j] = h[(size_t)row * 128 + j];
    sc[j] = h[(size_t)col * 128 + j];
    if (j < 16) srad[j] = g_rad[(size_t)eg * 16 + j] * g_ninv[r * 16 + j];
    if (j == 0) sea = ea_[eg];
    __syncthreads();
    float acc = bm1[j];
    for (int k = 0; k < 128; ++k) acc += sh[k] * Wm1[k * 128 + j];
    for (int k = 0; k < 128; ++k) acc += sc[k] * Wm1[(128 + k) * 128 + j];
    for (int q = 0; q < 16; ++q)  acc += srad[q] * Wm1[(256 + q) * 128 + j];
    acc += sea * Wm1[272 * 128 + j];
    g_v[(size_t)eg * 128 + j] = silu_f(acc);
}

// ---------------- generic 128->128 per-edge layer --------------------------
// mode 0: g_ef = act(g_v @ W); mode 1: g_v = act(g_ef @ W[r])
__global__ __launch_bounds__(128) void k_mlp(
    int mode, const float* __restrict__ Wb, long wstr,
    const float* __restrict__ bias, int bstr, int act) {
    __shared__ float sx[128];
    long long eg = blockIdx.x;
    int r = (int)(eg >> 15);
    int j = threadIdx.x;
    const float* X = mode ? g_ef : g_v;
    float* Y = mode ? g_v : g_ef;
    sx[j] = X[(size_t)eg * 128 + j];
    __syncthreads();
    const float* W = Wb + (size_t)r * wstr;
    float acc = bias ? bias[(size_t)r * bstr + j] : 0.f;
    for (int k = 0; k < 128; ++k) acc += sx[k] * W[k * 128 + j];
    Y[(size_t)eg * 128 + j] = act ? silu_f(acc) : acc;
}

// ---------------- phi + trans scatter: one block per edge ------------------
__global__ __launch_bounds__(128) void k_phi(
    const int* __restrict__ edges, const float* __restrict__ Wc2) {
    __shared__ float sw[128];
    __shared__ float sphi[4];
    long long eg = blockIdx.x;
    int r = (int)(eg >> 15);
    long long e = eg & (E_ - 1);
    int j = threadIdx.x;
    sw[j] = g_v[(size_t)eg * 128 + j];
    __syncthreads();
    if (j < 4) {
        float p = 0.f;
        for (int k = 0; k < 128; ++k) p += sw[k] * Wc2[(size_t)r * 512 + k * 4 + j];
        sphi[j] = p;
    }
    __syncthreads();
    if (j < 12) {
        int row = eidx(edges, (long long)(r * 2 + 0) * E_ + e);
        float v = g_cd[(size_t)eg * 12 + j] * sphi[j / 3];
        atomicAdd(&g_s[(size_t)row * 12 + j], v);
    }
}

// ---------------- agg scatter: one block per edge --------------------------
__global__ __launch_bounds__(128) void k_agg(
    const int* __restrict__ edges, const float* __restrict__ Wrel) {
    __shared__ float sx[128];
    long long eg = blockIdx.x;
    int r = (int)(eg >> 15);
    long long e = eg & (E_ - 1);
    int j = threadIdx.x;
    sx[j] = g_ef[(size_t)eg * 128 + j];
    __syncthreads();
    const float* W = Wrel + (size_t)r * 16384;
    float acc = 0.f;
    for (int k = 0; k < 128; ++k) acc += sx[k] * W[k * 128 + j];
    int row = eidx(edges, (long long)(r * 2 + 0) * E_ + e);
    atomicAdd(&g_agg[(size_t)row * 128 + j], acc);
}

// ---------------- node MLP: one block per node -----------------------------
__global__ __launch_bounds__(128) void k_node1(
    const float* __restrict__ h, const float* __restrict__ Wn1,
    const float* __restrict__ bn1) {
    __shared__ float sh[128], sa[128];
    int n = blockIdx.x, j = threadIdx.x;
    sh[j] = h[(size_t)n * 128 + j];
    sa[j] = g_agg[(size_t)n * 128 + j];
    __syncthreads();
    float acc = bn1[j];
    for (int k = 0; k < 128; ++k) acc += sh[k] * Wn1[k * 128 + j];
    for (int k = 0; k < 128; ++k) acc += sa[k] * Wn1[(128 + k) * 128 + j];
    g_z[(size_t)n * 128 + j] = silu_f(acc);
}

__global__ __launch_bounds__(128) void k_node2(
    const float* __restrict__ h, const float* __restrict__ Wn2,
    const float* __restrict__ bn2, float* __restrict__ out_h) {
    __shared__ float sz[128];
    int n = blockIdx.x, j = threadIdx.x;
    sz[j] = g_z[(size_t)n * 128 + j];
    __syncthreads();
    float acc = bn2[j];
    for (int k = 0; k < 128; ++k) acc += sz[k] * Wn2[k * 128 + j];
    float v = h[(size_t)n * 128 + j] + acc;
    g_hnew[(size_t)n * 128 + j] = v;
    out_h[(size_t)n * 128 + j] = v;
}

// ---------------- x output -------------------------------------------------
__global__ void k_x(const float* __restrict__ coord, float* __restrict__ outx) {
    int i = blockIdx.x * 256 + threadIdx.x;
    if (i < N_ * 12) {
        int n = i / 12;
        float cnt = fmaxf(g_cnt[n], 1.f);
        outx[i] = coord[i] + g_s[i] / cnt;
    }
}

// ---------------- m output: one block per edge -----------------------------
__global__ __launch_bounds__(128) void k_mfull(
    const int* __restrict__ edges, const float* __restrict__ ea_,
    const float* __restrict__ We1, const float* __restrict__ be1,
    const float* __restrict__ We2, const float* __restrict__ be2,
    float* __restrict__ out_m) {
    __shared__ float sh[128], sc[128];
    __shared__ float sea;
    __shared__ float spart[4];
    long long eg = blockIdx.x;
    int r = (int)(eg >> 15);
    long long e = eg & (E_ - 1);
    int j = threadIdx.x;
    int lane = j & 31, w = j >> 5;
    int row = eidx(edges, (long long)(r * 2 + 0) * E_ + e);
    int col = eidx(edges, (long long)(r * 2 + 1) * E_ + e);
    sh[j] = g_hnew[(size_t)row * 128 + j];
    sc[j] = g_hnew[(size_t)col * 128 + j];
    if (j == 0) sea = ea_[eg];
    __syncthreads();
    float acc = be1[j];
    for (int k = 0; k < 128; ++k) acc += sh[k] * We1[k * 128 + j];
    acc += sea * We1[128 * 128 + j];
    for (int k = 0; k < 128; ++k) acc += sc[k] * We1[(129 + k) * 128 + j];
    float t = silu_f(acc) * We2[j];
#pragma unroll
    for (int off = 16; off; off >>= 1) t += __shfl_xor_sync(0xffffffffu, t, off);
    if (lane == 0) spart[w] = t;
    __syncthreads();
    if (j == 0)
        out_m[eg] = spart[0] + spart[1] + spart[2] + spart[3] + be2[0];
}

// ---------------------------------------------------------------------------
extern "C" void kernel_launch(void* const* d_in, const int* in_sizes, int n_in,
                              void* d_out, int out_size) {
    // Expected element counts in reference-dict order.
    static const int EXPSZ[20] = {
        2560000,  // h
        240000,   // coord
        262144,   // edge_attr
        524288,   // edges
        34944,    // Wm1
        128,      // bm1
        16384,    // Wm2
        128,      // bm2
        32896,    // We1
        128,      // be1
        128,      // We2
        1,        // be2
        32768,    // Wn1
        128,      // bn1
        16384,    // Wn2
        128,      // bn2
        131072,   // Wrel
        131072,   // Wc1
        1024,     // bc1
        4096      // Wc2
    };
    const void* P[20];
    bool used[20] = {};
    for (int s = 0; s < 20; ++s) {
        P[s] = nullptr;
        for (int i = 0; i < n_in && i < 20; ++i) {
            if (!used[i] && in_sizes[i] == EXPSZ[s]) {
                P[s] = d_in[i];
                used[i] = true;
                break;
            }
        }
        if (!P[s] && s < n_in) P[s] = d_in[s];  // positional fallback
    }

    const float* h = (const float*)P[0];
    const float* coord = (const float*)P[1];
    const float* edge_attr = (const float*)P[2];
    const int* edges = (const int*)P[3];
    const float* Wm1 = (const float*)P[4];
    const float* bm1 = (const float*)P[5];
    const float* Wm2 = (const float*)P[6];
    const float* bm2 = (const float*)P[7];
    const float* We1 = (const float*)P[8];
    const float* be1 = (const float*)P[9];
    const float* We2 = (const float*)P[10];
    const float* be2 = (const float*)P[11];
    const float* Wn1 = (const float*)P[12];
    const float* bn1 = (const float*)P[13];
    const float* Wn2 = (const float*)P[14];
    const float* bn2 = (const float*)P[15];
    const float* Wrel = (const float*)P[16];
    const float* Wc1 = (const float*)P[17];
    const float* bc1 = (const float*)P[18];
    const float* Wc2 = (const float*)P[19];

    float* out = (float*)d_out;
    float* out_h = out;                       // N*128
    float* out_x = out + (size_t)N_ * 128;    // N*12
    float* out_m = out_x + (size_t)N_ * 12;   // R*E
    bool has_x = out_size >= N_ * 128 + N_ * 12;
    bool has_m = out_size >= N_ * 128 + N_ * 12 + (int)NE_;

    k_detect<<<1, 1>>>(edges);
    k_zero<<<256, 256>>>();
    k_geo<<<dim3(E_ / 256, R_), 256>>>(coord, edges);
    k_norm<<<1, 128>>>();

    // message MLP
    k_msg1<<<(unsigned)NE_, 128>>>(edges, h, edge_attr, Wm1, bm1);
    k_mlp<<<(unsigned)NE_, 128>>>(0, Wm2, 0, bm2, 0, 1);            // ef
    // coord MLP
    k_mlp<<<(unsigned)NE_, 128>>>(1, Wc1, 16384, bc1, 128, 1);      // w
    k_phi<<<(unsigned)NE_, 128>>>(edges, Wc2);
    // agg
    k_agg<<<(unsigned)NE_, 128>>>(edges, Wrel);
    // node MLP
    k_node1<<<N_, 128>>>(h, Wn1, bn1);
    k_node2<<<N_, 128>>>(h, Wn2, bn2, out_h);
    // x
    if (has_x) k_x<<<(N_ * 12 + 255) / 256, 256>>>(coord, out_x);
    // m
    if (has_m) k_mfull<<<(unsigned)NE_, 128>>>(edges, edge_attr, We1, be1,
                                               We2, be2, out_m);
}

// round 17
// speedup vs baseline: 2.9313x; 2.9313x over previous
#include <cuda_runtime.h>
#include <cstdint>

constexpr int N_  = 20000;
constexpr int E_  = 32768;
constexpr int R_  = 8;
constexpr long long NE_ = (long long)R_ * E_;   // 262144

// ---------------- scratch (static device globals; no runtime alloc) --------
// RULE (round-15 post-mortem): NEVER pass these directly as kernel args from
// host code — host sees the shadow symbol, not the device address. Resolve
// with cudaGetSymbolAddress in kernel_launch, or reference inside kernels.
__device__ __align__(16) float g_AB[(size_t)N_ * 256];   // [h@Wm1a | h@Wm1b]
__device__ __align__(16) float g_PQ[(size_t)N_ * 256];   // [hn@We1a | hn@We1b]
__device__ __align__(16) float g_v[(size_t)NE_ * 128];   // silu(t1), later w
__device__ __align__(16) float g_ef[(size_t)NE_ * 128];  // edge features
__device__ __align__(16) float g_cd[(size_t)NE_ * 12];
__device__ __align__(16) float g_rad[(size_t)NE_ * 16];
__device__ __align__(16) float g_s[N_ * 12];
__device__ __align__(16) float g_agg[N_ * 128];
__device__ __align__(16) float g_cnt[N_];
__device__ __align__(16) float g_norm2[128];
__device__ __align__(16) float g_ninv[128];
__device__ __align__(16) float g_hnew[N_ * 128];
__device__ __align__(16) float g_z[N_ * 128];
__device__ int g_e64;   // 1 if edges are int64 (LOAD-BEARING: round-14 fix)

__device__ __forceinline__ float silu_f(float x) {
    return x / (1.0f + __expf(-x));
}

__device__ __forceinline__ int eidx(const int* e32, long long i) {
    if (g_e64) return (int)(((const long long*)e32)[i]);
    return e32[i];
}

// ---------------- dtype probe ----------------------------------------------
__global__ void k_detect(const int* __restrict__ e32) {
    if (threadIdx.x == 0 && blockIdx.x == 0) {
        int all0 = 1;
        for (int i = 1; i < 1024; i += 2)
            if (e32[i] != 0) { all0 = 0; break; }
        g_e64 = all0;
    }
}

// ---------------- zero accumulators ----------------------------------------
__global__ void k_zero() {
    int idx = blockIdx.x * blockDim.x + threadIdx.x;
    int stride = gridDim.x * blockDim.x;
    for (int i = idx; i < N_ * 128; i += stride) g_agg[i] = 0.f;
    for (int i = idx; i < N_ * 12; i += stride) g_s[i] = 0.f;
    for (int i = idx; i < N_; i += stride) g_cnt[i] = 0.f;
    if (idx < 128) g_norm2[idx] = 0.f;
}

// ---------------- geometry: cd, radial (raw), norm2, cnt -------------------
__global__ void k_geo(const float* __restrict__ coord,
                      const int* __restrict__ edges) {
    __shared__ float s_n[16];
    int tid = threadIdx.x;
    int r = blockIdx.y;
    long long e = (long long)blockIdx.x * 256 + tid;
    if (tid < 16) s_n[tid] = 0.f;
    __syncthreads();
    long long eg = (long long)r * E_ + e;
    int row = eidx(edges, (long long)(r * 2 + 0) * E_ + e);
    int col = eidx(edges, (long long)(r * 2 + 1) * E_ + e);
    float cd[4][3];
#pragma unroll
    for (int c = 0; c < 4; ++c)
#pragma unroll
        for (int a = 0; a < 3; ++a) {
            cd[c][a] = coord[(size_t)row * 12 + c * 3 + a]
                     - coord[(size_t)col * 12 + c * 3 + a];
            g_cd[(size_t)eg * 12 + c * 3 + a] = cd[c][a];
        }
#pragma unroll
    for (int c = 0; c < 4; ++c)
#pragma unroll
        for (int d = 0; d < 4; ++d) {
            float v = cd[c][0] * cd[d][0] + cd[c][1] * cd[d][1] + cd[c][2] * cd[d][2];
            g_rad[(size_t)eg * 16 + c * 4 + d] = v;
            atomicAdd(&s_n[c * 4 + d], v * v);
        }
    atomicAdd(&g_cnt[row], 1.f);
    __syncthreads();
    if (tid < 16) atomicAdd(&g_norm2[r * 16 + tid], s_n[tid]);
}

__global__ void k_norm() {
    int i = threadIdx.x;
    if (i < 128) g_ninv[i] = 1.0f / fmaxf(sqrtf(g_norm2[i]), 1e-12f);
}

// ---------------- node GEMM (M=N_, K=128 or 256, N=128), tiled -------------
__global__ __launch_bounds__(256) void k_ngemm(
    const float* __restrict__ X0, const float* __restrict__ X1,
    const float* __restrict__ W, const float* __restrict__ bias,
    const float* __restrict__ resid, int act,
    float* __restrict__ Y, int ldy, int ycol, float* __restrict__ Y2) {
    __shared__ float sX[128 * 33];
    __shared__ float sW[32 * 128];
    int m0 = blockIdx.x * 128;
    int tid = threadIdx.x, tx = tid & 15, ty = tid >> 4;
    float acc[8][8];
#pragma unroll
    for (int i = 0; i < 8; ++i)
#pragma unroll
        for (int j = 0; j < 8; ++j) acc[i][j] = 0.f;
    int KB = X1 ? 8 : 4;
    for (int kb = 0; kb < KB; ++kb) {
        const float* Xp = (kb < 4) ? X0 : X1;
        int kc = (kb & 3) * 32;
        for (int i = tid; i < 128 * 32; i += 256) {
            int e = i >> 5, k = i & 31;
            int m = m0 + e;
            sX[e * 33 + k] = (m < N_) ? Xp[(size_t)m * 128 + kc + k] : 0.f;
        }
        for (int i = tid; i < 32 * 128; i += 256) sW[i] = W[kb * 32 * 128 + i];
        __syncthreads();
#pragma unroll 4
        for (int k = 0; k < 32; ++k) {
            float4 b0 = *(const float4*)(sW + k * 128 + tx * 8);
            float4 b1 = *(const float4*)(sW + k * 128 + tx * 8 + 4);
            float bv[8] = {b0.x, b0.y, b0.z, b0.w, b1.x, b1.y, b1.z, b1.w};
#pragma unroll
            for (int i = 0; i < 8; ++i) {
                float a = sX[(ty * 8 + i) * 33 + k];
#pragma unroll
                for (int j = 0; j < 8; ++j) acc[i][j] += a * bv[j];
            }
        }
        __syncthreads();
    }
#pragma unroll
    for (int i = 0; i < 8; ++i) {
        int m = m0 + ty * 8 + i;
        if (m >= N_) continue;
#pragma unroll
        for (int j = 0; j < 8; ++j) {
            int n = tx * 8 + j;
            float v = acc[i][j];
            if (bias) v += bias[n];
            if (act) v = silu_f(v);
            if (resid) v += resid[(size_t)m * 128 + n];
            Y[(size_t)m * ldy + ycol + n] = v;
            if (Y2) Y2[(size_t)m * 128 + n] = v;
        }
    }
}

// ---------------- msg first layer: v = silu(t1), warp per edge -------------
__global__ __launch_bounds__(256) void k_msg(
    const float* __restrict__ edge_attr, const int* __restrict__ edges,
    const float* __restrict__ Wm1, const float* __restrict__ bm1) {
    __shared__ float sWr[16 * 128];   // Wm1 radial rows 256..271
    __shared__ float sWe[128];        // Wm1 row 272 (ea)
    __shared__ float sB1[128];
    __shared__ float sRad[8][17];
    int tid = threadIdx.x;
    int w = tid >> 5, lane = tid & 31;
    for (int i = tid; i < 16 * 128; i += 256) sWr[i] = Wm1[256 * 128 + i];
    if (tid < 128) {
        sWe[tid] = Wm1[272 * 128 + tid];
        sB1[tid] = bm1[tid];
    }
    __syncthreads();

    long long eg = (long long)blockIdx.x * 8 + w;
    int r = (int)(eg >> 15);
    long long e = eg & (E_ - 1);
    if (lane < 16) sRad[w][lane] = g_rad[(size_t)eg * 16 + lane] * g_ninv[r * 16 + lane];
    __syncwarp();
    int row = eidx(edges, (long long)(r * 2 + 0) * E_ + e);
    int col = eidx(edges, (long long)(r * 2 + 1) * E_ + e);
    float ea = edge_attr[eg];
    int c0 = lane * 4;
    float4 a = *(const float4*)(g_AB + (size_t)row * 256 + c0);
    float4 b = *(const float4*)(g_AB + (size_t)col * 256 + 128 + c0);
    float t[4] = {a.x + b.x, a.y + b.y, a.z + b.z, a.w + b.w};
#pragma unroll
    for (int j = 0; j < 4; ++j) {
        int c = c0 + j;
        t[j] += sB1[c] + ea * sWe[c];
#pragma unroll
        for (int q = 0; q < 16; ++q) t[j] += sRad[w][q] * sWr[q * 128 + c];
        t[j] = silu_f(t[j]);
    }
    *(float4*)(g_v + (size_t)eg * 128 + c0) = make_float4(t[0], t[1], t[2], t[3]);
}

// ---------------- edge GEMM: Y = [silu](X @ W[r] + bias[r]) or agg-scatter -
__global__ __launch_bounds__(256) void k_egemm(
    const float* __restrict__ X, const float* __restrict__ Wbase, long wstride,
    const float* __restrict__ bias, int bstride, int act,
    float* __restrict__ Y, const int* __restrict__ edges, int do_agg) {
    __shared__ float sX[128 * 33];
    __shared__ float sW[32 * 128];
    __shared__ int sRow[128];
    int r = blockIdx.y;
    int e0 = blockIdx.x * 128;
    size_t egb = (size_t)r * E_ + e0;
    const float* W = Wbase + (size_t)r * wstride;
    int tid = threadIdx.x, tx = tid & 15, ty = tid >> 4;
    if (do_agg && tid < 128)
        sRow[tid] = eidx(edges, (long long)(r * 2 + 0) * E_ + e0 + tid);
    float acc[8][8];
#pragma unroll
    for (int i = 0; i < 8; ++i)
#pragma unroll
        for (int j = 0; j < 8; ++j) acc[i][j] = 0.f;
    for (int kb = 0; kb < 4; ++kb) {
        for (int i = tid; i < 128 * 32; i += 256) {
            int e = i >> 5, k = i & 31;
            sX[e * 33 + k] = X[(egb + e) * 128 + kb * 32 + k];
        }
        for (int i = tid; i < 32 * 128; i += 256) sW[i] = W[kb * 32 * 128 + i];
        __syncthreads();
#pragma unroll 4
        for (int k = 0; k < 32; ++k) {
            float4 b0 = *(const float4*)(sW + k * 128 + tx * 8);
            float4 b1 = *(const float4*)(sW + k * 128 + tx * 8 + 4);
            float bv[8] = {b0.x, b0.y, b0.z, b0.w, b1.x, b1.y, b1.z, b1.w};
#pragma unroll
            for (int i = 0; i < 8; ++i) {
                float a = sX[(ty * 8 + i) * 33 + k];
#pragma unroll
                for (int j = 0; j < 8; ++j) acc[i][j] += a * bv[j];
            }
        }
        __syncthreads();
    }
    if (do_agg) {
#pragma unroll
        for (int i = 0; i < 8; ++i) {
            int row = sRow[ty * 8 + i];
            float* dst = g_agg + (size_t)row * 128 + tx * 8;
#pragma unroll
            for (int j = 0; j < 8; ++j) atomicAdd(dst + j, acc[i][j]);
        }
    } else {
#pragma unroll
        for (int i = 0; i < 8; ++i) {
            int e = ty * 8 + i;
            float o[8];
#pragma unroll
            for (int j = 0; j < 8; ++j) {
                float v = acc[i][j];
                if (bias) v += bias[r * bstride + tx * 8 + j];
                o[j] = act ? silu_f(v) : v;
            }
            float* dst = Y + (egb + e) * 128 + tx * 8;
            *(float4*)dst = *(float4*)o;
            *(float4*)(dst + 4) = *(float4*)(o + 4);
        }
    }
}

// ---------------- phi + trans scatter (warp per edge) ----------------------
__global__ __launch_bounds__(256) void k_phi(
    const int* __restrict__ edges, const float* __restrict__ Wc2) {
    __shared__ __align__(16) float sWc2[512];
    int tid = threadIdx.x;
    int w = tid >> 5, lane = tid & 31;
    long long eg0 = (long long)blockIdx.x * 8;
    int r = (int)(eg0 >> 15);   // 8 edges per block share r
    for (int i = tid; i < 512; i += 256) sWc2[i] = Wc2[(size_t)r * 512 + i];
    __syncthreads();
    long long eg = eg0 + w;
    long long e = eg & (E_ - 1);
    int c0 = lane * 4;
    float4 wv = *(const float4*)(g_v + (size_t)eg * 128 + c0);
    float wvv[4] = {wv.x, wv.y, wv.z, wv.w};
    float p[4] = {0.f, 0.f, 0.f, 0.f};
#pragma unroll
    for (int j = 0; j < 4; ++j) {
        float4 wc = *(const float4*)(sWc2 + (c0 + j) * 4);
        p[0] += wvv[j] * wc.x;
        p[1] += wvv[j] * wc.y;
        p[2] += wvv[j] * wc.z;
        p[3] += wvv[j] * wc.w;
    }
#pragma unroll
    for (int off = 16; off; off >>= 1) {
#pragma unroll
        for (int cc = 0; cc < 4; ++cc)
            p[cc] += __shfl_xor_sync(0xffffffffu, p[cc], off);
    }
    if (lane < 12) {
        int row = eidx(edges, (long long)(r * 2 + 0) * E_ + e);
        int cc = lane / 3;
        float v = g_cd[(size_t)eg * 12 + lane] * p[cc];
        atomicAdd(&g_s[(size_t)row * 12 + lane], v);
    }
}

// ---------------- x output -------------------------------------------------
__global__ void k_x(const float* __restrict__ coord, float* __restrict__ outx) {
    int i = blockIdx.x * 256 + threadIdx.x;
    if (i < N_ * 12) {
        int n = i / 12;
        float cnt = fmaxf(g_cnt[n], 1.f);
        outx[i] = coord[i] + g_s[i] / cnt;
    }
}

// ---------------- m output: warp per edge ----------------------------------
__global__ void k_m(const int* __restrict__ edges,
                    const float* __restrict__ edge_attr,
                    const float* __restrict__ We1, const float* __restrict__ be1,
                    const float* __restrict__ We2, const float* __restrict__ be2,
                    float* __restrict__ outm) {
    int w = threadIdx.x >> 5, lane = threadIdx.x & 31;
    long long eg = (long long)blockIdx.x * 8 + w;
    int r = (int)(eg >> 15);
    long long e = eg & (E_ - 1);
    int row = eidx(edges, (long long)(r * 2 + 0) * E_ + e);
    int col = eidx(edges, (long long)(r * 2 + 1) * E_ + e);
    float ea = edge_attr[eg];
    int c = lane * 4;
    float4 p = *(const float4*)(g_PQ + (size_t)row * 256 + c);
    float4 q = *(const float4*)(g_PQ + (size_t)col * 256 + 128 + c);
    float4 we = *(const float4*)(We1 + 128 * 128 + c);
    float4 b = *(const float4*)(be1 + c);
    float4 w2 = *(const float4*)(We2 + c);
    float acc = silu_f(p.x + q.x + ea * we.x + b.x) * w2.x
              + silu_f(p.y + q.y + ea * we.y + b.y) * w2.y
              + silu_f(p.z + q.z + ea * we.z + b.z) * w2.z
              + silu_f(p.w + q.w + ea * we.w + b.w) * w2.w;
#pragma unroll
    for (int off = 16; off; off >>= 1) acc += __shfl_xor_sync(0xffffffffu, acc, off);
    if (lane == 0) outm[eg] = acc + be2[0];
}

// ---------------------------------------------------------------------------
extern "C" void kernel_launch(void* const* d_in, const int* in_sizes, int n_in,
                              void* d_out, int out_size) {
    // Size-based remap (LOAD-BEARING: round-14 fix). Reference-dict order.
    static const int EXPSZ[20] = {
        2560000, 240000, 262144, 524288, 34944, 128, 16384, 128,
        32896, 128, 128, 1, 32768, 128, 16384, 128, 131072, 131072, 1024, 4096
    };
    const void* P[20];
    bool used[20] = {};
    for (int s = 0; s < 20; ++s) {
        P[s] = nullptr;
        for (int i = 0; i < n_in && i < 20; ++i) {
            if (!used[i] && in_sizes[i] == EXPSZ[s]) {
                P[s] = d_in[i];
                used[i] = true;
                break;
            }
        }
        if (!P[s] && s < n_in) P[s] = d_in[s];
    }

    const float* h = (const float*)P[0];
    const float* coord = (const float*)P[1];
    const float* edge_attr = (const float*)P[2];
    const int* edges = (const int*)P[3];
    const float* Wm1 = (const float*)P[4];
    const float* bm1 = (const float*)P[5];
    const float* Wm2 = (const float*)P[6];
    const float* bm2 = (const float*)P[7];
    const float* We1 = (const float*)P[8];
    const float* be1 = (const float*)P[9];
    const float* We2 = (const float*)P[10];
    const float* be2 = (const float*)P[11];
    const float* Wn1 = (const float*)P[12];
    const float* bn1 = (const float*)P[13];
    const float* Wn2 = (const float*)P[14];
    const float* bn2 = (const float*)P[15];
    const float* Wrel = (const float*)P[16];
    const float* Wc1 = (const float*)P[17];
    const float* bc1 = (const float*)P[18];
    const float* Wc2 = (const float*)P[19];

    // LOAD-BEARING (round-15 fix): resolve REAL device addresses of the
    // __device__ scratch globals. Host-side symbol names alias the host
    // shadow (readable-as-zero via ATS on GB300) — never pass them raw.
    float *p_AB, *p_PQ, *p_v, *p_ef, *p_agg, *p_z, *p_hnew;
    cudaGetSymbolAddress((void**)&p_AB, g_AB);
    cudaGetSymbolAddress((void**)&p_PQ, g_PQ);
    cudaGetSymbolAddress((void**)&p_v, g_v);
    cudaGetSymbolAddress((void**)&p_ef, g_ef);
    cudaGetSymbolAddress((void**)&p_agg, g_agg);
    cudaGetSymbolAddress((void**)&p_z, g_z);
    cudaGetSymbolAddress((void**)&p_hnew, g_hnew);

    float* out = (float*)d_out;
    float* out_h = out;                       // N*128
    float* out_x = out + (size_t)N_ * 128;    // N*12
    float* out_m = out_x + (size_t)N_ * 12;   // R*E
    bool has_x = out_size >= N_ * 128 + N_ * 12;
    bool has_m = out_size >= N_ * 128 + N_ * 12 + (int)NE_;

    k_detect<<<1, 1>>>(edges);
    k_zero<<<256, 256>>>();
    k_geo<<<dim3(E_ / 256, R_), 256>>>(coord, edges);
    k_norm<<<1, 128>>>();

    int gN = (N_ + 127) / 128;
    // A|B = h @ Wm1[0:128] | h @ Wm1[128:256]
    k_ngemm<<<gN, 256>>>(h, nullptr, Wm1, nullptr, nullptr, 0, p_AB, 256, 0, nullptr);
    k_ngemm<<<gN, 256>>>(h, nullptr, Wm1 + 128 * 128, nullptr, nullptr, 0, p_AB, 256, 128, nullptr);

    // v = silu(msg_in @ Wm1 + bm1)
    k_msg<<<(unsigned)(NE_ / 8), 256>>>(edge_attr, edges, Wm1, bm1);
    // ef = silu(v @ Wm2 + bm2)
    k_egemm<<<dim3(E_ / 128, R_), 256>>>(p_v, Wm2, 0, bm2, 0, 1, p_ef, edges, 0);
    // w = silu(ef @ Wc1[r] + bc1[r])  (overwrite g_v)
    k_egemm<<<dim3(E_ / 128, R_), 256>>>(p_ef, Wc1, 128 * 128, bc1, 128, 1, p_v, edges, 0);
    // phi + trans scatter
    k_phi<<<(unsigned)(NE_ / 8), 256>>>(edges, Wc2);
    // agg += ef @ Wrel[r] scattered by row
    k_egemm<<<dim3(E_ / 128, R_), 256>>>(p_ef, Wrel, 128 * 128, nullptr, 0, 0, nullptr, edges, 1);

    if (has_x) k_x<<<(N_ * 12 + 255) / 256, 256>>>(coord, out_x);

    // z = silu([h|agg] @ Wn1 + bn1);  h_new = h + z @ Wn2 + bn2
    k_ngemm<<<gN, 256>>>(h, p_agg, Wn1, bn1, nullptr, 1, p_z, 128, 0, nullptr);
    k_ngemm<<<gN, 256>>>(p_z, nullptr, Wn2, bn2, h, 0, p_hnew, 128, 0, out_h);

    // P|Q = h_new @ We1[0:128] | h_new @ We1[129:257]
    k_ngemm<<<gN, 256>>>(p_hnew, nullptr, We1, nullptr, nullptr, 0, p_PQ, 256, 0, nullptr);
    k_ngemm<<<gN, 256>>>(p_hnew, nullptr, We1 + 129 * 128, nullptr, nullptr, 0, p_PQ, 256, 128, nullptr);

    if (has_m) k_m<<<(unsigned)(NE_ / 8), 256>>>(edges, edge_attr, We1, be1, We2, be2, out_m);
}